// round 2
// baseline (speedup 1.0000x reference)
#include <cuda_runtime.h>
#include <cstdint>

// Problem constants (fixed by the dataset instance).
#define BB 512
#define LL 512
#define CC 256
#define C4 (CC / 4)           // 64 float4 per channel row
#define NTHREADS 256
#define LGROUPS 4             // 256 threads / 64 float4-columns
#define PARTS 8               // L split into 8 chunks of 64 rows
#define ROWS_PER_PART (LL / PARTS)     // 64
#define TSLICES 8             // output-time split

// Least-squares constants for t = 0..511:
//   sum_t  = 130816, sum_t2 = 44608256, denom = sum_t2 - sum_t^2/n = 11184768
#define SUM_T     130816.0f
#define K1        255.5f          /* sum_t / n */
#define INV_DENOM (1.0f / 11184768.0f)
#define INV_N     (1.0f / 512.0f)

// Partial-sum scratch: [BB][PARTS][C4] float4, two arrays = 8 MiB total.
__device__ float4 g_psy [BB * PARTS * C4];
__device__ float4 g_psty[BB * PARTS * C4];

// ---------------------------------------------------------------------------
// Kernel A: pure-read reduction. grid = (BB, PARTS), block = 256.
// Each block reduces 64 L-rows of one batch into per-channel partials.
// ---------------------------------------------------------------------------
__global__ __launch_bounds__(NTHREADS, 8)
void lr_reduce_kernel(const float* __restrict__ x)
{
    const int b   = blockIdx.x;
    const int p   = blockIdx.y;
    const int tid = threadIdx.x;
    const int c4  = tid & (C4 - 1);
    const int lg  = tid >> 6;          // 0..3

    const float4* xb = reinterpret_cast<const float4*>(
                           x + (size_t)b * LL * CC) + c4;
    const int l0 = p * ROWS_PER_PART;

    float4 sy  = make_float4(0.f, 0.f, 0.f, 0.f);
    float4 sty = make_float4(0.f, 0.f, 0.f, 0.f);

    #pragma unroll
    for (int i = 0; i < ROWS_PER_PART / LGROUPS; i++) {   // 16 iters
        int l = l0 + lg + i * LGROUPS;
        float4 v = __ldg(&xb[(size_t)l * C4]);
        float tf = (float)l;
        sy.x += v.x;  sy.y += v.y;  sy.z += v.z;  sy.w += v.w;
        sty.x = fmaf(tf, v.x, sty.x);
        sty.y = fmaf(tf, v.y, sty.y);
        sty.z = fmaf(tf, v.z, sty.z);
        sty.w = fmaf(tf, v.w, sty.w);
    }

    __shared__ float4 s_sy [LGROUPS][C4];
    __shared__ float4 s_sty[LGROUPS][C4];
    s_sy [lg][c4] = sy;
    s_sty[lg][c4] = sty;
    __syncthreads();

    if (lg == 0) {
        float4 Sy  = s_sy [0][c4];
        float4 Sty = s_sty[0][c4];
        #pragma unroll
        for (int g = 1; g < LGROUPS; g++) {
            float4 a  = s_sy [g][c4];
            float4 t2 = s_sty[g][c4];
            Sy.x += a.x;   Sy.y += a.y;   Sy.z += a.z;   Sy.w += a.w;
            Sty.x += t2.x; Sty.y += t2.y; Sty.z += t2.z; Sty.w += t2.w;
        }
        const int idx = (b * PARTS + p) * C4 + c4;
        g_psy [idx] = Sy;
        g_psty[idx] = Sty;
    }
}

// ---------------------------------------------------------------------------
// Kernel B: pure-write forecast. grid = (BB, TSLICES), block = 256.
// Every thread finalizes slope/intercept for its float4 channel group
// (partials come from L2) and streams its t-slice of output.
// ---------------------------------------------------------------------------
__global__ __launch_bounds__(NTHREADS, 8)
void lr_forecast_kernel(float* __restrict__ out, int t_out_len)
{
    const int b   = blockIdx.x;
    const int s   = blockIdx.y;
    const int tid = threadIdx.x;
    const int c4  = tid & (C4 - 1);
    const int lg  = tid >> 6;

    float4 Sy  = make_float4(0.f, 0.f, 0.f, 0.f);
    float4 Sty = make_float4(0.f, 0.f, 0.f, 0.f);
    const int base = b * PARTS * C4 + c4;
    #pragma unroll
    for (int p = 0; p < PARTS; p++) {
        float4 a  = g_psy [base + p * C4];
        float4 t2 = g_psty[base + p * C4];
        Sy.x += a.x;   Sy.y += a.y;   Sy.z += a.z;   Sy.w += a.w;
        Sty.x += t2.x; Sty.y += t2.y; Sty.z += t2.z; Sty.w += t2.w;
    }

    float4 sl, ic;
    sl.x = (Sty.x - K1 * Sy.x) * INV_DENOM;
    sl.y = (Sty.y - K1 * Sy.y) * INV_DENOM;
    sl.z = (Sty.z - K1 * Sy.z) * INV_DENOM;
    sl.w = (Sty.w - K1 * Sy.w) * INV_DENOM;
    ic.x = (Sy.x - sl.x * SUM_T) * INV_N;
    ic.y = (Sy.y - sl.y * SUM_T) * INV_N;
    ic.z = (Sy.z - sl.z * SUM_T) * INV_N;
    ic.w = (Sy.w - sl.w * SUM_T) * INV_N;

    const int rows_per = (t_out_len + TSLICES - 1) / TSLICES;   // 76 for 608
    const int t0   = s * rows_per;
    const int tend = min(t0 + rows_per, t_out_len);

    float4* ob = reinterpret_cast<float4*>(
                     out + (size_t)b * t_out_len * CC) + c4;

    #pragma unroll 4
    for (int t = t0 + lg; t < tend; t += LGROUPS) {
        float tf = (float)t;
        float4 o;
        o.x = fmaf(sl.x, tf, ic.x);
        o.y = fmaf(sl.y, tf, ic.y);
        o.z = fmaf(sl.z, tf, ic.z);
        o.w = fmaf(sl.w, tf, ic.w);
        ob[(size_t)t * C4] = o;
    }
}

extern "C" void kernel_launch(void* const* d_in, const int* in_sizes, int n_in,
                              void* d_out, int out_size)
{
    const float* x = (const float*)d_in[0];
    float* out = (float*)d_out;
    int t_out_len = out_size / (BB * CC);   // 608 for pred_len = 96

    dim3 gridA(BB, PARTS);
    lr_reduce_kernel<<<gridA, NTHREADS>>>(x);

    dim3 gridB(BB, TSLICES);
    lr_forecast_kernel<<<gridB, NTHREADS>>>(out, t_out_len);
}

// round 3
// speedup vs baseline: 1.0543x; 1.0543x over previous
#include <cuda_runtime.h>
#include <cstdint>

// Problem constants (fixed by the dataset instance).
#define BB 512
#define LL 512
#define CC 256
#define C4 (CC / 4)            // 64 float4 per full channel row
#define NTHREADS 256
#define CSLICES 4              // channel split -> grid = 512*4 = 2048 blocks
#define C4S (C4 / CSLICES)     // 16 float4 per block slice
#define LGR (NTHREADS / C4S)   // 16 l-groups per block

// Least-squares constants for t = 0..511:
//   sum_t = 130816, sum_t2 = 44608256, denom = sum_t2 - sum_t^2/n = 11184768
#define SUM_T     130816.0f
#define K1        255.5f          /* sum_t / n */
#define INV_DENOM (1.0f / 11184768.0f)
#define INV_N     (1.0f / 512.0f)

__global__ __launch_bounds__(NTHREADS, 8)
void lr_forecast_fused(const float* __restrict__ x,
                       float* __restrict__ out,
                       int t_out_len)
{
    const int b   = blockIdx.x;            // batch
    const int cs  = blockIdx.y;            // channel slice 0..3
    const int tid = threadIdx.x;
    const int c4  = tid & (C4S - 1);       // 0..15  (float4 column within slice)
    const int lg  = tid >> 4;              // 0..15  (l-stride group)

    // ---- Pass 1: accumulate sum_y, sum_ty over this thread's l-stripe ----
    const float4* xb = reinterpret_cast<const float4*>(
                           x + (size_t)b * LL * CC + cs * (C4S * 4)) + c4;

    float4 sy  = make_float4(0.f, 0.f, 0.f, 0.f);
    float4 sty = make_float4(0.f, 0.f, 0.f, 0.f);

    #pragma unroll 8
    for (int l = lg; l < LL; l += LGR) {   // 32 iterations / thread
        float4 v = __ldcs(&xb[(size_t)l * C4]);
        float tf = (float)l;
        sy.x += v.x;  sy.y += v.y;  sy.z += v.z;  sy.w += v.w;
        sty.x = fmaf(tf, v.x, sty.x);
        sty.y = fmaf(tf, v.y, sty.y);
        sty.z = fmaf(tf, v.z, sty.z);
        sty.w = fmaf(tf, v.w, sty.w);
    }

    // ---- Reduce the 16 l-groups in shared memory ----
    __shared__ float4 s_sy [LGR][C4S];
    __shared__ float4 s_sty[LGR][C4S];
    __shared__ float4 s_slope[C4S];
    __shared__ float4 s_icept[C4S];

    s_sy [lg][c4] = sy;
    s_sty[lg][c4] = sty;
    __syncthreads();

    if (lg == 0) {
        float4 Sy  = s_sy [0][c4];
        float4 Sty = s_sty[0][c4];
        #pragma unroll
        for (int g = 1; g < LGR; g++) {
            float4 a  = s_sy [g][c4];
            float4 t2 = s_sty[g][c4];
            Sy.x += a.x;   Sy.y += a.y;   Sy.z += a.z;   Sy.w += a.w;
            Sty.x += t2.x; Sty.y += t2.y; Sty.z += t2.z; Sty.w += t2.w;
        }
        float4 sl, ic;
        sl.x = (Sty.x - K1 * Sy.x) * INV_DENOM;
        sl.y = (Sty.y - K1 * Sy.y) * INV_DENOM;
        sl.z = (Sty.z - K1 * Sy.z) * INV_DENOM;
        sl.w = (Sty.w - K1 * Sy.w) * INV_DENOM;
        ic.x = (Sy.x - sl.x * SUM_T) * INV_N;
        ic.y = (Sy.y - sl.y * SUM_T) * INV_N;
        ic.z = (Sy.z - sl.z * SUM_T) * INV_N;
        ic.w = (Sy.w - sl.w * SUM_T) * INV_N;
        s_slope[c4] = sl;
        s_icept[c4] = ic;
    }
    __syncthreads();

    // ---- Pass 2: stream out[b, t, cslice] = slope * t + intercept ----
    const float4 sl = s_slope[c4];
    const float4 ic = s_icept[c4];

    float4* ob = reinterpret_cast<float4*>(
                     out + (size_t)b * t_out_len * CC + cs * (C4S * 4)) + c4;

    #pragma unroll 8
    for (int t = lg; t < t_out_len; t += LGR) {   // 38 iterations / thread
        float tf = (float)t;
        float4 o;
        o.x = fmaf(sl.x, tf, ic.x);
        o.y = fmaf(sl.y, tf, ic.y);
        o.z = fmaf(sl.z, tf, ic.z);
        o.w = fmaf(sl.w, tf, ic.w);
        __stcs(&ob[(size_t)t * C4], o);
    }
}

extern "C" void kernel_launch(void* const* d_in, const int* in_sizes, int n_in,
                              void* d_out, int out_size)
{
    const float* x = (const float*)d_in[0];
    float* out = (float*)d_out;
    int t_out_len = out_size / (BB * CC);   // 608 for pred_len = 96

    dim3 grid(BB, CSLICES);
    lr_forecast_fused<<<grid, NTHREADS>>>(x, out, t_out_len);
}